// round 3
// baseline (speedup 1.0000x reference)
#include <cuda_runtime.h>
#include <cstdint>

// Problem constants (from reference)
#define B_  4
#define L_  2048
#define H_  8
#define E_  64
#define BM  128   // query rows per block == threads per block
#define BN  32    // key rows per tile

// ---------------- packed f32x2 helpers (sm_100a FFMA2 path) ----------------
__device__ __forceinline__ unsigned long long f2_pack(float a, float b) {
    unsigned long long r;
    asm("mov.b64 %0, {%1, %2};"
        : "=l"(r) : "r"(__float_as_uint(a)), "r"(__float_as_uint(b)));
    return r;
}
__device__ __forceinline__ void f2_unpack(unsigned long long v, float& a, float& b) {
    unsigned int lo, hi;
    asm("mov.b64 {%0, %1}, %2;" : "=r"(lo), "=r"(hi) : "l"(v));
    a = __uint_as_float(lo);
    b = __uint_as_float(hi);
}
__device__ __forceinline__ unsigned long long f2_fma(unsigned long long a,
                                                     unsigned long long b,
                                                     unsigned long long c) {
    unsigned long long d;
    asm("fma.rn.f32x2 %0, %1, %2, %3;" : "=l"(d) : "l"(a), "l"(b), "l"(c));
    return d;
}
__device__ __forceinline__ unsigned long long f2_mul(unsigned long long a,
                                                     unsigned long long b) {
    unsigned long long d;
    asm("mul.rn.f32x2 %0, %1, %2;" : "=l"(d) : "l"(a), "l"(b));
    return d;
}

// ---------------- one KV tile: scores + online softmax + PV ----------------
template <bool MASKED>
__device__ __forceinline__ void tile_step(
    const unsigned long long* __restrict__ q2,   // [E_/2] packed query row
    unsigned long long* __restrict__ o2,         // [E_/2] packed output accum
    float& mrow, float& lsum,
    const float* __restrict__ Ks,                // smem [BN][E_]
    const float* __restrict__ Vs,                // smem [BN][E_]
    const float* __restrict__ brow,              // bias + l*L + j0 (global, L2)
    int l, int j0, float scale)
{
    float t[BN];

    // scores: t[j] = q . K[j]
    const ulonglong2* K2 = reinterpret_cast<const ulonglong2*>(Ks);
    #pragma unroll
    for (int j = 0; j < BN; ++j) {
        unsigned long long a0 = 0ull, a1 = 0ull;  // (0.f,0.f)
        #pragma unroll
        for (int e = 0; e < E_ / 4; ++e) {
            ulonglong2 kk = K2[j * (E_ / 4) + e];
            a0 = f2_fma(q2[2 * e],     kk.x, a0);
            a1 = f2_fma(q2[2 * e + 1], kk.y, a1);
        }
        float x0, x1, y0, y1;
        f2_unpack(a0, x0, x1);
        f2_unpack(a1, y0, y1);
        t[j] = (x0 + y0) + (x1 + y1);
    }

    // additive bias, then scale (reference: softmax(scale * (qk + bias)))
    #pragma unroll
    for (int j4 = 0; j4 < BN / 4; ++j4) {
        float4 b4 = reinterpret_cast<const float4*>(brow)[j4];
        t[4 * j4 + 0] = (t[4 * j4 + 0] + b4.x) * scale;
        t[4 * j4 + 1] = (t[4 * j4 + 1] + b4.y) * scale;
        t[4 * j4 + 2] = (t[4 * j4 + 2] + b4.z) * scale;
        t[4 * j4 + 3] = (t[4 * j4 + 3] + b4.w) * scale;
    }

    if (MASKED) {
        #pragma unroll
        for (int j = 0; j < BN; ++j)
            if (j0 + j > l) t[j] = -3.0e38f;
    }

    // online softmax update
    float tmax = t[0];
    #pragma unroll
    for (int j = 1; j < BN; ++j) tmax = fmaxf(tmax, t[j]);
    float mnew  = fmaxf(mrow, tmax);
    float alpha = __expf(mrow - mnew);   // mrow=-3e38 first tile -> alpha=0
    lsum *= alpha;
    unsigned long long al2 = f2_pack(alpha, alpha);
    #pragma unroll
    for (int i = 0; i < E_ / 2; ++i) o2[i] = f2_mul(o2[i], al2);

    // P @ V
    const ulonglong2* V2 = reinterpret_cast<const ulonglong2*>(Vs);
    #pragma unroll
    for (int j = 0; j < BN; ++j) {
        float p = __expf(t[j] - mnew);   // masked t -> p = 0
        lsum += p;
        unsigned long long p2 = f2_pack(p, p);
        #pragma unroll
        for (int e = 0; e < E_ / 4; ++e) {
            ulonglong2 vv = V2[j * (E_ / 4) + e];
            o2[2 * e]     = f2_fma(p2, vv.x, o2[2 * e]);
            o2[2 * e + 1] = f2_fma(p2, vv.y, o2[2 * e + 1]);
        }
    }
    mrow = mnew;
}

// ---------------- kernel: one query row per thread, flash style ------------
__global__ void __launch_bounds__(BM, 2) causal_attn_kernel(
    const float* __restrict__ q, const float* __restrict__ k,
    const float* __restrict__ v, const float* __restrict__ bias,
    float* __restrict__ out)
{
    __shared__ float Ks[BN * E_];
    __shared__ float Vs[BN * E_];

    const int tid = threadIdx.x;
    // reverse mapping: heaviest (most KV tiles) query blocks launch first
    const int qt  = (int)gridDim.x - 1 - (int)blockIdx.x;
    const int r0  = qt * BM;
    const int bh  = blockIdx.y;
    const int b   = bh / H_;
    const int h   = bh % H_;
    const int l   = r0 + tid;

    const float scale = 0.125f;  // 1/sqrt(64)

    // load query row into packed registers
    unsigned long long q2[E_ / 2];
    {
        const ulonglong2* qp = reinterpret_cast<const ulonglong2*>(
            q + (((size_t)b * L_ + l) * H_ + h) * (size_t)E_);
        #pragma unroll
        for (int i = 0; i < E_ / 4; ++i) {
            ulonglong2 t = qp[i];
            q2[2 * i]     = t.x;
            q2[2 * i + 1] = t.y;
        }
    }

    unsigned long long o2[E_ / 2];
    #pragma unroll
    for (int i = 0; i < E_ / 2; ++i) o2[i] = 0ull;
    float mrow = -3.0e38f;
    float lsum = 0.0f;

    const int jend_full = r0;        // tiles [0, r0): no masking needed
    const int jend      = r0 + BM;   // tiles [r0, r0+BM): per-element mask

    for (int j0 = 0; j0 < jend; j0 += BN) {
        __syncthreads();  // protect previous tile's smem reads
        // cooperative K/V tile load: 512 float4 each, 4 per thread
        #pragma unroll
        for (int i = 0; i < (BN * E_ / 4) / BM; ++i) {
            int idx = i * BM + tid;          // float4 index in tile
            int j   = idx >> 4;              // 16 float4 per 64-float row
            int e4  = idx & 15;
            size_t g = (((size_t)b * L_ + (size_t)(j0 + j)) * H_ + h) * (size_t)E_
                       + (size_t)e4 * 4;
            reinterpret_cast<float4*>(Ks)[idx] =
                *reinterpret_cast<const float4*>(k + g);
            reinterpret_cast<float4*>(Vs)[idx] =
                *reinterpret_cast<const float4*>(v + g);
        }
        __syncthreads();

        const float* brow = bias + (size_t)l * L_ + j0;
        if (j0 < jend_full)
            tile_step<false>(q2, o2, mrow, lsum, Ks, Vs, brow, l, j0, scale);
        else
            tile_step<true>(q2, o2, mrow, lsum, Ks, Vs, brow, l, j0, scale);
    }

    // epilogue: normalize and store (B,L,H,E) fp32
    float inv = 1.0f / lsum;
    float2* op = reinterpret_cast<float2*>(
        out + (((size_t)b * L_ + l) * H_ + h) * (size_t)E_);
    #pragma unroll
    for (int i = 0; i < E_ / 2; ++i) {
        float a, c;
        f2_unpack(o2[i], a, c);
        op[i] = make_float2(a * inv, c * inv);
    }
}

extern "C" void kernel_launch(void* const* d_in, const int* in_sizes, int n_in,
                              void* d_out, int out_size)
{
    const float* q    = (const float*)d_in[0];  // (B,L,H,E)
    const float* k    = (const float*)d_in[1];  // (B,L,H,E)
    const float* v    = (const float*)d_in[2];  // (B,L,H,E)
    // d_in[3] = attn_mask: fixed triu(k=1) causal mask, computed analytically
    const float* bias = (const float*)d_in[4];  // (L,L) causal-graph logits

    float* out = (float*)d_out;                 // (B,L,H,E) fp32

    dim3 grid(L_ / BM, B_ * H_);
    causal_attn_kernel<<<grid, BM>>>(q, k, v, bias, out);
}

// round 4
// speedup vs baseline: 1.4825x; 1.4825x over previous
#include <cuda_runtime.h>
#include <cstdint>

typedef unsigned long long ull;

#define B_   4
#define L_   2048
#define H_   8
#define E_   64
#define BM   64          // query rows per block
#define BN   32          // keys per tile
#define NT   128         // threads per block
#define ROWS 512         // H_*E_ (float stride between consecutive l)
#define PSTR 36          // padded P row stride (floats): 144B, 16B aligned

// ---------------- packed f32x2 helpers (FFMA2 path) ----------------
__device__ __forceinline__ void f2_unpack(ull v, float& a, float& b) {
    unsigned int lo, hi;
    asm("mov.b64 {%0, %1}, %2;" : "=r"(lo), "=r"(hi) : "l"(v));
    a = __uint_as_float(lo);
    b = __uint_as_float(hi);
}
__device__ __forceinline__ ull f2_dup(float a) {
    ull r;
    asm("mov.b64 %0, {%1, %1};" : "=l"(r) : "r"(__float_as_uint(a)));
    return r;
}
__device__ __forceinline__ ull f2_fma(ull a, ull b, ull c) {
    ull d;
    asm("fma.rn.f32x2 %0, %1, %2, %3;" : "=l"(d) : "l"(a), "l"(b), "l"(c));
    return d;
}
__device__ __forceinline__ ull f2_mul(ull a, ull b) {
    ull d;
    asm("mul.rn.f32x2 %0, %1, %2;" : "=l"(d) : "l"(a), "l"(b));
    return d;
}

// ---------------- kernel ----------------
__global__ void __launch_bounds__(NT, 4) causal_attn_kernel(
    const float* __restrict__ q, const float* __restrict__ k,
    const float* __restrict__ v, const float* __restrict__ bias,
    float* __restrict__ out)
{
    // smem: Q/K pair-transposed over head-dim pairs; V row-major pairs; P padded
    __shared__ float2 Qs2[32][BM];   // [e2][r]      16 KB
    __shared__ float2 Ks2[32][BN];   // [e2][c]       8 KB
    __shared__ float2 Vs2[BN][32];   // [j][e2]       8 KB
    __shared__ float  Ps[BM][PSTR];  //               9 KB

    const int t  = threadIdx.x;
    const int tr = t >> 3;           // 0..15  (row group)
    const int tc = t & 7;            // 0..7   (col lane)
    const int rbase = tr << 2;       // first owned row in tile

    const int qt = (int)gridDim.x - 1 - (int)blockIdx.x;  // heavy blocks first
    const int r0 = qt * BM;
    const int bh = blockIdx.y;
    const int b  = bh >> 3;
    const int h  = bh & 7;

    const float scale = 0.125f;      // 1/sqrt(64)
    const size_t base = (size_t)b * L_ * ROWS + (size_t)h * E_;
    const float* qb = q + base;
    const float* kb = k + base;
    const float* vb = v + base;
    float*       ob = out + base;

    // ---- Q block -> smem, pair-transposed (once) ----
    #pragma unroll
    for (int it = 0; it < 8; ++it) {
        int idx = it * NT + t;               // 0..1023
        int r   = idx & (BM - 1);
        int e4  = idx >> 6;                  // 0..15
        float4 qv = *(const float4*)(qb + (size_t)(r0 + r) * ROWS + (e4 << 2));
        Qs2[2 * e4][r]     = make_float2(qv.x, qv.y);
        Qs2[2 * e4 + 1][r] = make_float2(qv.z, qv.w);
    }

    ull o2[4][4];
    #pragma unroll
    for (int rr = 0; rr < 4; ++rr)
        #pragma unroll
        for (int i = 0; i < 4; ++i) o2[rr][i] = 0ull;
    float m[4]    = {-3.0e38f, -3.0e38f, -3.0e38f, -3.0e38f};
    float lsum[4] = {0.f, 0.f, 0.f, 0.f};

    const int nfull  = r0 >> 5;      // tiles with no masking
    const int ntiles = nfull + 2;    // +2 diagonal tiles

    for (int tile = 0; tile < ntiles; ++tile) {
        const int j0 = tile << 5;
        __syncthreads();             // protect previous tile's K/V reads

        // K tile: pair-transposed store (c-fast split, conflict-free STS)
        #pragma unroll
        for (int it = 0; it < 4; ++it) {
            int idx = it * NT + t;
            int c   = idx & 31;
            int e4  = idx >> 5;
            float4 kv = *(const float4*)(kb + (size_t)(j0 + c) * ROWS + (e4 << 2));
            Ks2[2 * e4][c]     = make_float2(kv.x, kv.y);
            Ks2[2 * e4 + 1][c] = make_float2(kv.z, kv.w);
        }
        // V tile: straight copy (e4-fast split, coalesced LDG + STS.128)
        #pragma unroll
        for (int it = 0; it < 4; ++it) {
            int idx = it * NT + t;
            int e4  = idx & 15;
            int c   = idx >> 4;
            float4 vv = *(const float4*)(vb + (size_t)(j0 + c) * ROWS + (e4 << 2));
            *(float4*)(&Vs2[c][2 * e4]) = vv;
        }
        // bias prefetch (hides L2 latency under QK)
        float bb[4][4];
        #pragma unroll
        for (int rr = 0; rr < 4; ++rr) {
            const float* bp = bias + (size_t)(r0 + rbase + rr) * L_ + j0 + tc;
            #pragma unroll
            for (int i = 0; i < 4; ++i) bb[rr][i] = __ldg(bp + (i << 3));
        }
        __syncthreads();

        // ---- S = Q K^T : 4x4 micro-tile, f32x2 over e-pairs ----
        ull acc[4][4];
        #pragma unroll
        for (int rr = 0; rr < 4; ++rr)
            #pragma unroll
            for (int i = 0; i < 4; ++i) acc[rr][i] = 0ull;

        #pragma unroll 8
        for (int e2 = 0; e2 < 32; ++e2) {
            ulonglong2 qa = *(const ulonglong2*)(&Qs2[e2][rbase]);
            ulonglong2 qc = *(const ulonglong2*)(&Qs2[e2][rbase + 2]);
            ull k0 = *(const ull*)(&Ks2[e2][tc]);
            ull k1 = *(const ull*)(&Ks2[e2][tc + 8]);
            ull k2 = *(const ull*)(&Ks2[e2][tc + 16]);
            ull k3 = *(const ull*)(&Ks2[e2][tc + 24]);
            acc[0][0] = f2_fma(qa.x, k0, acc[0][0]);
            acc[0][1] = f2_fma(qa.x, k1, acc[0][1]);
            acc[0][2] = f2_fma(qa.x, k2, acc[0][2]);
            acc[0][3] = f2_fma(qa.x, k3, acc[0][3]);
            acc[1][0] = f2_fma(qa.y, k0, acc[1][0]);
            acc[1][1] = f2_fma(qa.y, k1, acc[1][1]);
            acc[1][2] = f2_fma(qa.y, k2, acc[1][2]);
            acc[1][3] = f2_fma(qa.y, k3, acc[1][3]);
            acc[2][0] = f2_fma(qc.x, k0, acc[2][0]);
            acc[2][1] = f2_fma(qc.x, k1, acc[2][1]);
            acc[2][2] = f2_fma(qc.x, k2, acc[2][2]);
            acc[2][3] = f2_fma(qc.x, k3, acc[2][3]);
            acc[3][0] = f2_fma(qc.y, k0, acc[3][0]);
            acc[3][1] = f2_fma(qc.y, k1, acc[3][1]);
            acc[3][2] = f2_fma(qc.y, k2, acc[3][2]);
            acc[3][3] = f2_fma(qc.y, k3, acc[3][3]);
        }

        // ---- online softmax (row stats shared across the 8 tc-lanes) ----
        #pragma unroll
        for (int rr = 0; rr < 4; ++rr) {
            float tv[4];
            #pragma unroll
            for (int i = 0; i < 4; ++i) {
                float lo, hi;
                f2_unpack(acc[rr][i], lo, hi);
                tv[i] = ((lo + hi) + bb[rr][i]) * scale;
            }
            if (tile >= nfull) {
                const int growr = r0 + rbase + rr;
                #pragma unroll
                for (int i = 0; i < 4; ++i)
                    if (j0 + tc + (i << 3) > growr) tv[i] = -3.0e38f;
            }
            float mx = fmaxf(fmaxf(tv[0], tv[1]), fmaxf(tv[2], tv[3]));
            mx = fmaxf(mx, __shfl_xor_sync(0xffffffffu, mx, 1));
            mx = fmaxf(mx, __shfl_xor_sync(0xffffffffu, mx, 2));
            mx = fmaxf(mx, __shfl_xor_sync(0xffffffffu, mx, 4));
            float mnew  = fmaxf(m[rr], mx);
            float alpha = __expf(m[rr] - mnew);
            m[rr] = mnew;
            float p0 = __expf(tv[0] - mnew);
            float p1 = __expf(tv[1] - mnew);
            float p2 = __expf(tv[2] - mnew);
            float p3 = __expf(tv[3] - mnew);
            lsum[rr] = lsum[rr] * alpha + ((p0 + p1) + (p2 + p3));
            ull a2 = f2_dup(alpha);
            #pragma unroll
            for (int i = 0; i < 4; ++i) o2[rr][i] = f2_mul(o2[rr][i], a2);
            Ps[rbase + rr][tc]      = p0;
            Ps[rbase + rr][tc + 8]  = p1;
            Ps[rbase + rr][tc + 16] = p2;
            Ps[rbase + rr][tc + 24] = p3;
        }
        __syncwarp();   // P rows produced & consumed within this warp

        // ---- O += P V ----
        #pragma unroll 2
        for (int jq = 0; jq < 8; ++jq) {
            float4 pr[4];
            #pragma unroll
            for (int rr = 0; rr < 4; ++rr)
                pr[rr] = *(const float4*)(&Ps[rbase + rr][jq << 2]);
            #pragma unroll
            for (int jj = 0; jj < 4; ++jj) {
                const int j = (jq << 2) + jj;
                ull v0 = *(const ull*)(&Vs2[j][tc]);
                ull v1 = *(const ull*)(&Vs2[j][tc + 8]);
                ull v2 = *(const ull*)(&Vs2[j][tc + 16]);
                ull v3 = *(const ull*)(&Vs2[j][tc + 24]);
                #pragma unroll
                for (int rr = 0; rr < 4; ++rr) {
                    float pj = (jj == 0) ? pr[rr].x :
                               (jj == 1) ? pr[rr].y :
                               (jj == 2) ? pr[rr].z : pr[rr].w;
                    ull p2 = f2_dup(pj);
                    o2[rr][0] = f2_fma(p2, v0, o2[rr][0]);
                    o2[rr][1] = f2_fma(p2, v1, o2[rr][1]);
                    o2[rr][2] = f2_fma(p2, v2, o2[rr][2]);
                    o2[rr][3] = f2_fma(p2, v3, o2[rr][3]);
                }
            }
        }
    }

    // ---- epilogue: finish lsum across lanes, normalize, store ----
    #pragma unroll
    for (int rr = 0; rr < 4; ++rr) {
        float ls = lsum[rr];
        ls += __shfl_xor_sync(0xffffffffu, ls, 1);
        ls += __shfl_xor_sync(0xffffffffu, ls, 2);
        ls += __shfl_xor_sync(0xffffffffu, ls, 4);
        float inv = 1.0f / ls;
        float* orow = ob + (size_t)(r0 + rbase + rr) * ROWS;
        #pragma unroll
        for (int i = 0; i < 4; ++i) {
            float lo, hi;
            f2_unpack(o2[rr][i], lo, hi);
            int e = (tc + (i << 3)) << 1;
            *(float2*)(orow + e) = make_float2(lo * inv, hi * inv);
        }
    }
}

extern "C" void kernel_launch(void* const* d_in, const int* in_sizes, int n_in,
                              void* d_out, int out_size)
{
    const float* q    = (const float*)d_in[0];  // (B,L,H,E)
    const float* k    = (const float*)d_in[1];  // (B,L,H,E)
    const float* v    = (const float*)d_in[2];  // (B,L,H,E)
    // d_in[3] = attn_mask: fixed triu(k=1), handled analytically
    const float* bias = (const float*)d_in[4];  // (L,L)

    float* out = (float*)d_out;                 // (B,L,H,E) fp32

    dim3 grid(L_ / BM, B_ * H_);
    causal_attn_kernel<<<grid, NT>>>(q, k, v, bias, out);
}

// round 5
// speedup vs baseline: 1.5773x; 1.0640x over previous
#include <cuda_runtime.h>
#include <cstdint>

typedef unsigned long long ull;

#define B_    4
#define L_    2048
#define H_    8
#define E_    64
#define BM    64          // query rows per block
#define BN    32          // keys per tile
#define NT    128         // threads per block
#define ROWS  512         // H_*E_ (float stride between consecutive l)
#define KPAD  68          // K smem row stride (floats): bank-conflict-free
#define VTW   34          // Vt row width (float2): 272B stride, conflict-free
#define PSTR  36          // padded P row stride (floats)

// ---------------- packed f32x2 helpers (FFMA2 path) ----------------
__device__ __forceinline__ void f2_unpack(ull v, float& a, float& b) {
    unsigned int lo, hi;
    asm("mov.b64 {%0, %1}, %2;" : "=r"(lo), "=r"(hi) : "l"(v));
    a = __uint_as_float(lo);
    b = __uint_as_float(hi);
}
__device__ __forceinline__ ull f2_dup(float a) {
    ull r;
    asm("mov.b64 %0, {%1, %1};" : "=l"(r) : "r"(__float_as_uint(a)));
    return r;
}
__device__ __forceinline__ ull f2_fma(ull a, ull b, ull c) {
    ull d;
    asm("fma.rn.f32x2 %0, %1, %2, %3;" : "=l"(d) : "l"(a), "l"(b), "l"(c));
    return d;
}
__device__ __forceinline__ ull f2_mul(ull a, ull b) {
    ull d;
    asm("mul.rn.f32x2 %0, %1, %2;" : "=l"(d) : "l"(a), "l"(b));
    return d;
}

// ---------------- kernel ----------------
__global__ void __launch_bounds__(NT, 3) causal_attn_kernel(
    const float* __restrict__ q, const float* __restrict__ k,
    const float* __restrict__ v, const float* __restrict__ bias,
    float* __restrict__ out)
{
    __shared__ __align__(16) float2 Qs2[32][BM];   // [e2][r]          16 KB
    __shared__ __align__(16) float  Ks[BN][KPAD];  // row-major padded 8.5 KB
    __shared__ __align__(16) float2 Vt[32][VTW];   // [e2][j] padded   8.5 KB
    __shared__ __align__(16) float  Ps[BM][PSTR];  //                  9 KB

    const int t  = threadIdx.x;
    const int tr = t >> 3;            // 0..15
    const int tc = t & 7;             // 0..7
    const int rbase = tr << 2;        // first owned row

    const int qt = (int)gridDim.x - 1 - (int)blockIdx.x;   // heavy first
    const int r0 = qt * BM;
    const int bh = blockIdx.y;
    const int b  = bh >> 3;
    const int h  = bh & 7;

    const float scale = 0.125f;       // 1/sqrt(64)
    const size_t base = (size_t)b * L_ * ROWS + (size_t)h * E_;
    const float* qb = q + base;
    const float* kb = k + base;
    const float* vb = v + base;
    float*       ob = out + base;

    // ---- Q block -> smem, pair-transposed (once) ----
    #pragma unroll
    for (int it = 0; it < 8; ++it) {
        int idx = it * NT + t;                // 0..1023
        int r   = idx & (BM - 1);
        int e4  = idx >> 6;                   // 0..15
        float4 qv = *(const float4*)(qb + (size_t)(r0 + r) * ROWS + (e4 << 2));
        Qs2[2 * e4][r]     = make_float2(qv.x, qv.y);
        Qs2[2 * e4 + 1][r] = make_float2(qv.z, qv.w);
    }

    ull o2[4][4];
    #pragma unroll
    for (int rr = 0; rr < 4; ++rr)
        #pragma unroll
        for (int i = 0; i < 4; ++i) o2[rr][i] = 0ull;
    float m[4]    = {-3.0e38f, -3.0e38f, -3.0e38f, -3.0e38f};
    float lsum[4] = {0.f, 0.f, 0.f, 0.f};

    const int nfull  = r0 >> 5;
    const int ntiles = nfull + 2;

    // cooperative-load coordinates (fixed per thread)
    const int lc = t >> 4;            // 0..7  (base row within tile)
    const int le = t & 15;            // 0..15 (float4 column)

    // ---- prefetch tile 0 into registers ----
    float4 kreg[4], vreg[4];
    #pragma unroll
    for (int it = 0; it < 4; ++it) {
        size_t g = (size_t)(lc + 8 * it) * ROWS + (le << 2);
        kreg[it] = *(const float4*)(kb + g);
        vreg[it] = *(const float4*)(vb + g);
    }

    for (int tile = 0; tile < ntiles; ++tile) {
        const int j0 = tile << 5;
        __syncthreads();              // previous tile's smem reads done

        // ---- STS prefetched K/V tile ----
        #pragma unroll
        for (int it = 0; it < 4; ++it) {
            int c = lc + 8 * it;
            *(float4*)(&Ks[c][le << 2]) = kreg[it];
            Vt[2 * le][c]     = make_float2(vreg[it].x, vreg[it].y);
            Vt[2 * le + 1][c] = make_float2(vreg[it].z, vreg[it].w);
        }
        __syncthreads();

        // ---- issue LDG for NEXT tile (latency hidden under compute) ----
        if (tile + 1 < ntiles) {
            const int jn = (tile + 1) << 5;
            #pragma unroll
            for (int it = 0; it < 4; ++it) {
                size_t g = (size_t)(jn + lc + 8 * it) * ROWS + (le << 2);
                kreg[it] = *(const float4*)(kb + g);
                vreg[it] = *(const float4*)(vb + g);
            }
        }
        // bias prefetch (consumed at softmax; hidden under QK)
        float bb[4][4];
        #pragma unroll
        for (int rr = 0; rr < 4; ++rr) {
            const float* bp = bias + (size_t)(r0 + rbase + rr) * L_ + j0 + tc;
            #pragma unroll
            for (int i = 0; i < 4; ++i) bb[rr][i] = __ldg(bp + (i << 3));
        }

        // ---- S = Q K^T : 4x4 micro-tile, 2 e-pairs per step ----
        ull acc[4][4];
        #pragma unroll
        for (int rr = 0; rr < 4; ++rr)
            #pragma unroll
            for (int i = 0; i < 4; ++i) acc[rr][i] = 0ull;

        #pragma unroll 4
        for (int g = 0; g < 16; ++g) {
            ulonglong2 qa0 = *(const ulonglong2*)(&Qs2[2 * g][rbase]);
            ulonglong2 qc0 = *(const ulonglong2*)(&Qs2[2 * g][rbase + 2]);
            ulonglong2 qa1 = *(const ulonglong2*)(&Qs2[2 * g + 1][rbase]);
            ulonglong2 qc1 = *(const ulonglong2*)(&Qs2[2 * g + 1][rbase + 2]);
            ulonglong2 k0 = *(const ulonglong2*)(&Ks[tc][g << 2]);
            ulonglong2 k1 = *(const ulonglong2*)(&Ks[tc + 8][g << 2]);
            ulonglong2 k2 = *(const ulonglong2*)(&Ks[tc + 16][g << 2]);
            ulonglong2 k3 = *(const ulonglong2*)(&Ks[tc + 24][g << 2]);
            // e2 = 2g
            acc[0][0] = f2_fma(qa0.x, k0.x, acc[0][0]);
            acc[0][1] = f2_fma(qa0.x, k1.x, acc[0][1]);
            acc[0][2] = f2_fma(qa0.x, k2.x, acc[0][2]);
            acc[0][3] = f2_fma(qa0.x, k3.x, acc[0][3]);
            acc[1][0] = f2_fma(qa0.y, k0.x, acc[1][0]);
            acc[1][1] = f2_fma(qa0.y, k1.x, acc[1][1]);
            acc[1][2] = f2_fma(qa0.y, k2.x, acc[1][2]);
            acc[1][3] = f2_fma(qa0.y, k3.x, acc[1][3]);
            acc[2][0] = f2_fma(qc0.x, k0.x, acc[2][0]);
            acc[2][1] = f2_fma(qc0.x, k1.x, acc[2][1]);
            acc[2][2] = f2_fma(qc0.x, k2.x, acc[2][2]);
            acc[2][3] = f2_fma(qc0.x, k3.x, acc[2][3]);
            acc[3][0] = f2_fma(qc0.y, k0.x, acc[3][0]);
            acc[3][1] = f2_fma(qc0.y, k1.x, acc[3][1]);
            acc[3][2] = f2_fma(qc0.y, k2.x, acc[3][2]);
            acc[3][3] = f2_fma(qc0.y, k3.x, acc[3][3]);
            // e2 = 2g+1
            acc[0][0] = f2_fma(qa1.x, k0.y, acc[0][0]);
            acc[0][1] = f2_fma(qa1.x, k1.y, acc[0][1]);
            acc[0][2] = f2_fma(qa1.x, k2.y, acc[0][2]);
            acc[0][3] = f2_fma(qa1.x, k3.y, acc[0][3]);
            acc[1][0] = f2_fma(qa1.y, k0.y, acc[1][0]);
            acc[1][1] = f2_fma(qa1.y, k1.y, acc[1][1]);
            acc[1][2] = f2_fma(qa1.y, k2.y, acc[1][2]);
            acc[1][3] = f2_fma(qa1.y, k3.y, acc[1][3]);
            acc[2][0] = f2_fma(qc1.x, k0.y, acc[2][0]);
            acc[2][1] = f2_fma(qc1.x, k1.y, acc[2][1]);
            acc[2][2] = f2_fma(qc1.x, k2.y, acc[2][2]);
            acc[2][3] = f2_fma(qc1.x, k3.y, acc[2][3]);
            acc[3][0] = f2_fma(qc1.y, k0.y, acc[3][0]);
            acc[3][1] = f2_fma(qc1.y, k1.y, acc[3][1]);
            acc[3][2] = f2_fma(qc1.y, k2.y, acc[3][2]);
            acc[3][3] = f2_fma(qc1.y, k3.y, acc[3][3]);
        }

        // ---- online softmax ----
        #pragma unroll
        for (int rr = 0; rr < 4; ++rr) {
            float tv[4];
            #pragma unroll
            for (int i = 0; i < 4; ++i) {
                float lo, hi;
                f2_unpack(acc[rr][i], lo, hi);
                tv[i] = ((lo + hi) + bb[rr][i]) * scale;
            }
            if (tile >= nfull) {
                const int growr = r0 + rbase + rr;
                #pragma unroll
                for (int i = 0; i < 4; ++i)
                    if (j0 + tc + (i << 3) > growr) tv[i] = -3.0e38f;
            }
            float mx = fmaxf(fmaxf(tv[0], tv[1]), fmaxf(tv[2], tv[3]));
            mx = fmaxf(mx, __shfl_xor_sync(0xffffffffu, mx, 1));
            mx = fmaxf(mx, __shfl_xor_sync(0xffffffffu, mx, 2));
            mx = fmaxf(mx, __shfl_xor_sync(0xffffffffu, mx, 4));
            float mnew  = fmaxf(m[rr], mx);
            float alpha = __expf(m[rr] - mnew);
            m[rr] = mnew;
            float p0 = __expf(tv[0] - mnew);
            float p1 = __expf(tv[1] - mnew);
            float p2 = __expf(tv[2] - mnew);
            float p3 = __expf(tv[3] - mnew);
            lsum[rr] = lsum[rr] * alpha + ((p0 + p1) + (p2 + p3));
            ull a2 = f2_dup(alpha);
            #pragma unroll
            for (int i = 0; i < 4; ++i) o2[rr][i] = f2_mul(o2[rr][i], a2);
            Ps[rbase + rr][tc]      = p0;
            Ps[rbase + rr][tc + 8]  = p1;
            Ps[rbase + rr][tc + 16] = p2;
            Ps[rbase + rr][tc + 24] = p3;
        }
        __syncwarp();   // P produced & consumed within this warp

        // ---- O += P V : V pair-transposed, 2 keys per LDS.128 ----
        #pragma unroll 2
        for (int jq = 0; jq < 8; ++jq) {
            float4 pr[4];
            ull pd[4][4];
            #pragma unroll
            for (int rr = 0; rr < 4; ++rr) {
                pr[rr] = *(const float4*)(&Ps[rbase + rr][jq << 2]);
                pd[rr][0] = f2_dup(pr[rr].x);
                pd[rr][1] = f2_dup(pr[rr].y);
                pd[rr][2] = f2_dup(pr[rr].z);
                pd[rr][3] = f2_dup(pr[rr].w);
            }
            #pragma unroll
            for (int i = 0; i < 4; ++i) {
                const int e2 = tc + (i << 3);
                ulonglong2 va = *(const ulonglong2*)(&Vt[e2][jq << 2]);      // j, j+1
                ulonglong2 vb2 = *(const ulonglong2*)(&Vt[e2][(jq << 2) + 2]); // j+2, j+3
                #pragma unroll
                for (int rr = 0; rr < 4; ++rr) {
                    o2[rr][i] = f2_fma(pd[rr][0], va.x,  o2[rr][i]);
                    o2[rr][i] = f2_fma(pd[rr][1], va.y,  o2[rr][i]);
                    o2[rr][i] = f2_fma(pd[rr][2], vb2.x, o2[rr][i]);
                    o2[rr][i] = f2_fma(pd[rr][3], vb2.y, o2[rr][i]);
                }
            }
        }
    }

    // ---- epilogue: reduce lsum across lanes, normalize, store ----
    #pragma unroll
    for (int rr = 0; rr < 4; ++rr) {
        float ls = lsum[rr];
        ls += __shfl_xor_sync(0xffffffffu, ls, 1);
        ls += __shfl_xor_sync(0xffffffffu, ls, 2);
        ls += __shfl_xor_sync(0xffffffffu, ls, 4);
        float inv = 1.0f / ls;
        float* orow = ob + (size_t)(r0 + rbase + rr) * ROWS;
        #pragma unroll
        for (int i = 0; i < 4; ++i) {
            float lo, hi;
            f2_unpack(o2[rr][i], lo, hi);
            int e = (tc + (i << 3)) << 1;
            *(float2*)(orow + e) = make_float2(lo * inv, hi * inv);
        }
    }
}

extern "C" void kernel_launch(void* const* d_in, const int* in_sizes, int n_in,
                              void* d_out, int out_size)
{
    const float* q    = (const float*)d_in[0];  // (B,L,H,E)
    const float* k    = (const float*)d_in[1];  // (B,L,H,E)
    const float* v    = (const float*)d_in[2];  // (B,L,H,E)
    // d_in[3] = attn_mask: fixed triu(k=1), handled analytically
    const float* bias = (const float*)d_in[4];  // (L,L)

    float* out = (float*)d_out;                 // (B,L,H,E) fp32

    dim3 grid(L_ / BM, B_ * H_);
    causal_attn_kernel<<<grid, NT>>>(q, k, v, bias, out);
}

// round 7
// speedup vs baseline: 2.1901x; 1.3885x over previous
#include <cuda_runtime.h>
#include <cuda_bf16.h>
#include <cstdint>

typedef unsigned long long ull;
typedef unsigned int u32;

#define B_    4
#define L_    2048
#define H_    8
#define E_    64
#define BM    64          // query rows per block
#define BN    32          // keys per tile
#define NT    128         // 4 warps
#define ROWS  512         // H_*E_ float stride between consecutive l
#define PSTR  36          // P row stride (floats)

// ---- static smem layout (bytes). Q region aliases the tile region. ----
#define OFF_KHI  0                         // 32 x 128B bf16 (swizzled)
#define OFF_KLO  4096
#define OFF_V    8192                      // 32 x 68 fp32
#define OFF_PS   (8192 + 32*68*4)          // 16896; P 64 x 36 fp32
#define OFF_AL   (OFF_PS + BM*PSTR*4)      // 26112
#define OFF_LS   (OFF_AL + 256)            // 26368
#define SMEM_TOTAL (OFF_LS + 256)          // 26624
#define OFF_QHI  0                         // 64 x 128B (prologue only)
#define OFF_QLO  8192

// ---------------- packed f32x2 helpers ----------------
__device__ __forceinline__ void f2_unpack(ull v, float& a, float& b) {
    unsigned int lo, hi;
    asm("mov.b64 {%0, %1}, %2;" : "=r"(lo), "=r"(hi) : "l"(v));
    a = __uint_as_float(lo);
    b = __uint_as_float(hi);
}
__device__ __forceinline__ ull f2_dup(float a) {
    ull r;
    asm("mov.b64 %0, {%1, %1};" : "=l"(r) : "r"(__float_as_uint(a)));
    return r;
}
__device__ __forceinline__ ull f2_fma(ull a, ull b, ull c) {
    ull d;
    asm("fma.rn.f32x2 %0, %1, %2, %3;" : "=l"(d) : "l"(a), "l"(b), "l"(c));
    return d;
}
__device__ __forceinline__ ull f2_mul(ull a, ull b) {
    ull d;
    asm("mul.rn.f32x2 %0, %1, %2;" : "=l"(d) : "l"(a), "l"(b));
    return d;
}

// ---------------- tensor-core wrappers (baseline sm_80+ ISA) ----------------
__device__ __forceinline__ u32 smem_u32(const void* p) {
    u32 a;
    asm("{ .reg .u64 t; cvta.to.shared.u64 t, %1; cvt.u32.u64 %0, t; }"
        : "=r"(a) : "l"(p));
    return a;
}
__device__ __forceinline__ void ldsm4(u32 r[4], u32 addr) {
    asm volatile("ldmatrix.sync.aligned.m8n8.x4.shared.b16 {%0,%1,%2,%3}, [%4];"
                 : "=r"(r[0]), "=r"(r[1]), "=r"(r[2]), "=r"(r[3]) : "r"(addr));
}
__device__ __forceinline__ void mma16816(float c[4], const u32 a[4], u32 b0, u32 b1) {
    asm volatile(
        "mma.sync.aligned.m16n8k16.row.col.f32.bf16.bf16.f32 "
        "{%0,%1,%2,%3}, {%4,%5,%6,%7}, {%8,%9}, {%0,%1,%2,%3};"
        : "+f"(c[0]), "+f"(c[1]), "+f"(c[2]), "+f"(c[3])
        : "r"(a[0]), "r"(a[1]), "r"(a[2]), "r"(a[3]), "r"(b0), "r"(b1));
}

// split 8 floats into packed bf16 hi / lo (uint4 each, elem0 in low half)
__device__ __forceinline__ void splitpack8(float4 a, float4 b, uint4& hh, uint4& ll) {
    float f[8] = {a.x, a.y, a.z, a.w, b.x, b.y, b.z, b.w};
    u32 hw[8], lw[8];
    #pragma unroll
    for (int i = 0; i < 8; ++i) {
        u32 hb = (u32)__bfloat16_as_ushort(__float2bfloat16_rn(f[i]));
        float hf = __uint_as_float(hb << 16);
        lw[i] = (u32)__bfloat16_as_ushort(__float2bfloat16_rn(f[i] - hf));
        hw[i] = hb;
    }
    hh = make_uint4(hw[0] | (hw[1] << 16), hw[2] | (hw[3] << 16),
                    hw[4] | (hw[5] << 16), hw[6] | (hw[7] << 16));
    ll = make_uint4(lw[0] | (lw[1] << 16), lw[2] | (lw[3] << 16),
                    lw[4] | (lw[5] << 16), lw[6] | (lw[7] << 16));
}

// ---------------- kernel ----------------
__global__ void __launch_bounds__(NT, 3) causal_attn_kernel(
    const float* __restrict__ q, const float* __restrict__ k,
    const float* __restrict__ v, const float* __restrict__ bias,
    float* __restrict__ out)
{
    __shared__ __align__(128) char smem[SMEM_TOTAL];
    float* smemf = reinterpret_cast<float*>(smem);
    const u32 sb = smem_u32(smem);

    const int t    = threadIdx.x;
    const int lane = t & 31;
    const int w    = t >> 5;
    const int gid  = lane >> 2;      // 0..7
    const int tid4 = lane & 3;       // 0..3
    const int wrow = w << 4;         // warp's first S row (block-local)

    // PV ownership
    const int tr = t >> 3;           // 0..15
    const int tc = t & 7;            // 0..7
    const int rbase = tr << 2;       // 4 rows per thread

    const int qt = (int)gridDim.x - 1 - (int)blockIdx.x;   // heavy first
    const int r0 = qt * BM;
    const int bh = blockIdx.y;
    const int b  = bh >> 3;
    const int h  = bh & 7;

    const float scale = 0.125f;
    const size_t base = (size_t)b * L_ * ROWS + (size_t)h * E_;
    const float* qb = q + base;
    const float* kb = k + base;
    const float* vb = v + base;
    float*       ob = out + base;

    // ---- Q prologue: fp32 -> bf16 hi/lo, swizzled smem ----
    {
        const int row = t >> 1, half = t & 1;
        const float* qrow = qb + (size_t)(r0 + row) * ROWS + 32 * half;
        #pragma unroll
        for (int i = 0; i < 4; ++i) {
            float4 a  = *(const float4*)(qrow + 8 * i);
            float4 b4 = *(const float4*)(qrow + 8 * i + 4);
            uint4 hh, ll;
            splitpack8(a, b4, hh, ll);
            int c = 4 * half + i;                     // 16B chunk index
            u32 off = (u32)(row * 128 + 16 * (c ^ (row & 7)));
            *reinterpret_cast<uint4*>(smem + OFF_QHI + off) = hh;
            *reinterpret_cast<uint4*>(smem + OFF_QLO + off) = ll;
        }
    }
    __syncthreads();

    // ---- A fragments (held in registers for all tiles) ----
    u32 aH[4][4], aL[4][4];
    {
        const int rowL = wrow + (lane & 15);
        const int csel = lane >> 4;                   // 0/1: k-halves
        #pragma unroll
        for (int ks = 0; ks < 4; ++ks) {
            u32 off = (u32)(rowL * 128 + 16 * (((2 * ks + csel) ^ (rowL & 7))));
            ldsm4(aH[ks], sb + OFF_QHI + off);
            ldsm4(aL[ks], sb + OFF_QLO + off);
        }
    }
    __syncthreads();   // Q smem dead; tile region may be overwritten

    // ---- per-thread state ----
    ull o2[4][4];
    #pragma unroll
    for (int rr = 0; rr < 4; ++rr)
        #pragma unroll
        for (int i = 0; i < 4; ++i) o2[rr][i] = 0ull;
    float m1 = -3.0e38f, m2 = -3.0e38f, ls1 = 0.f, ls2 = 0.f;
    const int gr1 = r0 + wrow + gid;       // softmax row 1 (global)
    const int gr2 = gr1 + 8;

    const int nfull  = r0 >> 5;
    const int ntiles = nfull + 2;

    // K/V cooperative-load coords
    const int krow = t >> 2, kq = t & 3;   // K rows / e-quarters
    const int vc0  = t >> 4, ve4 = t & 15; // V rows / float4 cols

    // prefetch tile 0
    float4 kpre[4], vpre[4];
    #pragma unroll
    for (int i = 0; i < 4; ++i)
        kpre[i] = *(const float4*)(kb + (size_t)krow * ROWS + kq * 16 + i * 4);
    #pragma unroll
    for (int i = 0; i < 4; ++i)
        vpre[i] = *(const float4*)(vb + (size_t)(vc0 + 8 * i) * ROWS + ve4 * 4);

    // B-fragment ldmatrix per-lane address pieces (constant across tiles)
    const int bg    = lane >> 3;                         // matrix id 0..3
    const int bjoff = 8 * (bg >> 1) + (lane & 7);        // row within 16-j pair
    const int bcs   = bg & 1;                            // k-half select

    for (int tile = 0; tile < ntiles; ++tile) {
        const int j0 = tile << 5;
        __syncthreads();               // previous tile fully consumed

        // ---- STS K hi/lo (swizzled bf16) + V (fp32) ----
        {
            uint4 hh0, ll0, hh1, ll1;
            splitpack8(kpre[0], kpre[1], hh0, ll0);
            splitpack8(kpre[2], kpre[3], hh1, ll1);
            u32 o0 = (u32)(krow * 128 + 16 * ((2 * kq)     ^ (krow & 7)));
            u32 o1 = (u32)(krow * 128 + 16 * ((2 * kq + 1) ^ (krow & 7)));
            *reinterpret_cast<uint4*>(smem + OFF_KHI + o0) = hh0;
            *reinterpret_cast<uint4*>(smem + OFF_KHI + o1) = hh1;
            *reinterpret_cast<uint4*>(smem + OFF_KLO + o0) = ll0;
            *reinterpret_cast<uint4*>(smem + OFF_KLO + o1) = ll1;
            #pragma unroll
            for (int i = 0; i < 4; ++i)
                *(float4*)(smemf + OFF_V / 4 + (vc0 + 8 * i) * 68 + ve4 * 4) = vpre[i];
        }
        __syncthreads();

        // ---- prefetch next K/V (latency hidden under mma) ----
        if (tile + 1 < ntiles) {
            const int jn = (tile + 1) << 5;
            #pragma unroll
            for (int i = 0; i < 4; ++i)
                kpre[i] = *(const float4*)(kb + (size_t)(jn + krow) * ROWS + kq * 16 + i * 4);
            #pragma unroll
            for (int i = 0; i < 4; ++i)
                vpre[i] = *(const float4*)(vb + (size_t)(jn + vc0 + 8 * i) * ROWS + ve4 * 4);
        }
        // bias for this thread's fragment cols
        float2 bb1[4], bb2[4];
        {
            const float* bp1 = bias + (size_t)gr1 * L_ + j0 + 2 * tid4;
            const float* bp2 = bias + (size_t)gr2 * L_ + j0 + 2 * tid4;
            #pragma unroll
            for (int nt = 0; nt < 4; ++nt) {
                bb1[nt] = __ldg((const float2*)(bp1 + 8 * nt));
                bb2[nt] = __ldg((const float2*)(bp2 + 8 * nt));
            }
        }

        // ---- S = Q K^T on tensor cores (bf16x3) ----
        float cS[4][4];
        #pragma unroll
        for (int nt = 0; nt < 4; ++nt)
            #pragma unroll
            for (int i = 0; i < 4; ++i) cS[nt][i] = 0.f;

        #pragma unroll
        for (int ks = 0; ks < 4; ++ks) {
            #pragma unroll
            for (int ntp = 0; ntp < 2; ++ntp) {
                const int jrow = 16 * ntp + bjoff;
                u32 off = (u32)(jrow * 128 + 16 * (((2 * ks + bcs) ^ (jrow & 7))));
                u32 bhm[4], blm[4];
                ldsm4(bhm, sb + OFF_KHI + off);
                ldsm4(blm, sb + OFF_KLO + off);
                mma16816(cS[2 * ntp],     aH[ks], bhm[0], bhm[1]);
                mma16816(cS[2 * ntp],     aH[ks], blm[0], blm[1]);
                mma16816(cS[2 * ntp],     aL[ks], bhm[0], bhm[1]);
                mma16816(cS[2 * ntp + 1], aH[ks], bhm[2], bhm[3]);
                mma16816(cS[2 * ntp + 1], aH[ks], blm[2], blm[3]);
                mma16816(cS[2 * ntp + 1], aL[ks], bhm[2], bhm[3]);
            }
        }

        // ---- softmax on fragments (rows gr1, gr2; 8 cols each) ----
        float tv1[8], tv2[8];
        #pragma unroll
        for (int nt = 0; nt < 4; ++nt) {
            tv1[2 * nt]     = (cS[nt][0] + bb1[nt].x) * scale;
            tv1[2 * nt + 1] = (cS[nt][1] + bb1[nt].y) * scale;
            tv2[2 * nt]     = (cS[nt][2] + bb2[nt].x) * scale;
            tv2[2 * nt + 1] = (cS[nt][3] + bb2[nt].y) * scale;
        }
        if (tile >= nfull) {
            #pragma unroll
            for (int nt = 0; nt < 4; ++nt) {
                int c0 = j0 + 8 * nt + 2 * tid4;
                if (c0     > gr1) tv1[2 * nt]     = -3.0e38f;
                if (c0 + 1 > gr1) tv1[2 * nt + 1] = -3.0e38f;
                if (c0     > gr2) tv2[2 * nt]     = -3.0e38f;
                if (c0 + 1 > gr2) tv2[2 * nt + 1] = -3.0e38f;
            }
        }
        float mx1 = tv1[0], mx2 = tv2[0];
        #pragma unroll
        for (int i = 1; i < 8; ++i) {
            mx1 = fmaxf(mx1, tv1[i]);
            mx2 = fmaxf(mx2, tv2[i]);
        }
        mx1 = fmaxf(mx1, __shfl_xor_sync(0xffffffffu, mx1, 1));
        mx1 = fmaxf(mx1, __shfl_xor_sync(0xffffffffu, mx1, 2));
        mx2 = fmaxf(mx2, __shfl_xor_sync(0xffffffffu, mx2, 1));
        mx2 = fmaxf(mx2, __shfl_xor_sync(0xffffffffu, mx2, 2));
        float mn1 = fmaxf(m1, mx1), mn2 = fmaxf(m2, mx2);
        float alpha1 = __expf(m1 - mn1), alpha2 = __expf(m2 - mn2);
        m1 = mn1; m2 = mn2;
        float ps1 = 0.f, ps2 = 0.f;
        #pragma unroll
        for (int i = 0; i < 8; ++i) {
            tv1[i] = __expf(tv1[i] - mn1); ps1 += tv1[i];
            tv2[i] = __expf(tv2[i] - mn2); ps2 += tv2[i];
        }
        ps1 += __shfl_xor_sync(0xffffffffu, ps1, 1);
        ps1 += __shfl_xor_sync(0xffffffffu, ps1, 2);
        ps2 += __shfl_xor_sync(0xffffffffu, ps2, 1);
        ps2 += __shfl_xor_sync(0xffffffffu, ps2, 2);
        ls1 = ls1 * alpha1 + ps1;
        ls2 = ls2 * alpha2 + ps2;

        // ---- write P + alpha (consumed within this warp) ----
        {
            float* p1 = smemf + OFF_PS / 4 + (wrow + gid) * PSTR + 2 * tid4;
            float* p2 = smemf + OFF_PS / 4 + (wrow + gid + 8) * PSTR + 2 * tid4;
            #pragma unroll
            for (int nt = 0; nt < 4; ++nt) {
                *(float2*)(p1 + 8 * nt) = make_float2(tv1[2 * nt], tv1[2 * nt + 1]);
                *(float2*)(p2 + 8 * nt) = make_float2(tv2[2 * nt], tv2[2 * nt + 1]);
            }
            if (tid4 == 0) {
                smemf[OFF_AL / 4 + wrow + gid]     = alpha1;
                smemf[OFF_AL / 4 + wrow + gid + 8] = alpha2;
            }
        }
        __syncwarp();

        // ---- O scale by alpha ----
        #pragma unroll
        for (int rr = 0; rr < 4; ++rr) {
            ull a2 = f2_dup(smemf[OFF_AL / 4 + rbase + rr]);
            #pragma unroll
            for (int i = 0; i < 4; ++i) o2[rr][i] = f2_mul(o2[rr][i], a2);
        }

        // ---- O += P V (scalar f32x2) ----
        #pragma unroll 2
        for (int jq = 0; jq < 8; ++jq) {
            float4 pr[4];
            #pragma unroll
            for (int rr = 0; rr < 4; ++rr)
                pr[rr] = *(const float4*)(smemf + OFF_PS / 4 + (rbase + rr) * PSTR + (jq << 2));
            #pragma unroll
            for (int jj = 0; jj < 4; ++jj) {
                const int j = (jq << 2) + jj;
                const float* vrow = smemf + OFF_V / 4 + j * 68;
                ull v0 = *(const ull*)(vrow + 2 * tc);
                ull v1 = *(const ull*)(vrow + 2 * (tc + 8));
                ull v2 = *(const ull*)(vrow + 2 * (tc + 16));
                ull v3 = *(const ull*)(vrow + 2 * (tc + 24));
                #pragma unroll
                for (int rr = 0; rr < 4; ++rr) {
                    float pj = (jj == 0) ? pr[rr].x :
                               (jj == 1) ? pr[rr].y :
                               (jj == 2) ? pr[rr].z : pr[rr].w;
                    ull p2 = f2_dup(pj);
                    o2[rr][0] = f2_fma(p2, v0, o2[rr][0]);
                    o2[rr][1] = f2_fma(p2, v1, o2[rr][1]);
                    o2[rr][2] = f2_fma(p2, v2, o2[rr][2]);
                    o2[rr][3] = f2_fma(p2, v3, o2[rr][3]);
                }
            }
        }
    }

    // ---- epilogue ----
    if (tid4 == 0) {
        smemf[OFF_LS / 4 + wrow + gid]     = ls1;
        smemf[OFF_LS / 4 + wrow + gid + 8] = ls2;
    }
    __syncwarp();
    #pragma unroll
    for (int rr = 0; rr < 4; ++rr) {
        float inv = 1.0f / smemf[OFF_LS / 4 + rbase + rr];
        float* orow = ob + (size_t)(r0 + rbase + rr) * ROWS;
        #pragma unroll
        for (int i = 0; i < 4; ++i) {
            float lo, hi;
            f2_unpack(o2[rr][i], lo, hi);
            int e = (tc + (i << 3)) << 1;
            *(float2*)(orow + e) = make_float2(lo * inv, hi * inv);
        }
    }
}

extern "C" void kernel_launch(void* const* d_in, const int* in_sizes, int n_in,
                              void* d_out, int out_size)
{
    const float* q    = (const float*)d_in[0];  // (B,L,H,E)
    const float* k    = (const float*)d_in[1];  // (B,L,H,E)
    const float* v    = (const float*)d_in[2];  // (B,L,H,E)
    // d_in[3] = attn_mask: fixed triu(k=1), handled analytically
    const float* bias = (const float*)d_in[4];  // (L,L)

    float* out = (float*)d_out;                 // (B,L,H,E) fp32

    dim3 grid(L_ / BM, B_ * H_);
    causal_attn_kernel<<<grid, NT>>>(q, k, v, bias, out);
}

// round 8
// speedup vs baseline: 3.1349x; 1.4314x over previous
#include <cuda_runtime.h>
#include <cuda_bf16.h>
#include <cstdint>

typedef unsigned long long ull;
typedef unsigned int u32;

#define B_    4
#define L_    2048
#define H_    8
#define E_    64
#define BM    64          // query rows per block
#define BN    32          // keys per tile
#define NT    128         // 4 warps
#define ROWS  512         // H_*E_ float stride between consecutive l

// ---- static smem layout (bytes). Q prologue aliases the K/V region. ----
#define OFF_KHI  0                 // 32 x 128B bf16 (swizzled)
#define OFF_KLO  4096
#define OFF_VHI  8192              // 32 x 128B bf16 (swizzled)
#define OFF_VLO  12288
#define SMEM_TOTAL 16384
#define OFF_QHI  0                 // 64 x 128B (prologue only)
#define OFF_QLO  8192

// ---------------- tensor-core wrappers (baseline sm_80+ ISA) ----------------
__device__ __forceinline__ u32 smem_u32(const void* p) {
    u32 a;
    asm("{ .reg .u64 t; cvta.to.shared.u64 t, %1; cvt.u32.u64 %0, t; }"
        : "=r"(a) : "l"(p));
    return a;
}
__device__ __forceinline__ void ldsm4(u32 r[4], u32 addr) {
    asm volatile("ldmatrix.sync.aligned.m8n8.x4.shared.b16 {%0,%1,%2,%3}, [%4];"
                 : "=r"(r[0]), "=r"(r[1]), "=r"(r[2]), "=r"(r[3]) : "r"(addr));
}
__device__ __forceinline__ void ldsm4t(u32 r[4], u32 addr) {
    asm volatile("ldmatrix.sync.aligned.m8n8.x4.trans.shared.b16 {%0,%1,%2,%3}, [%4];"
                 : "=r"(r[0]), "=r"(r[1]), "=r"(r[2]), "=r"(r[3]) : "r"(addr));
}
__device__ __forceinline__ void mma16816(float c[4], const u32 a[4], u32 b0, u32 b1) {
    asm volatile(
        "mma.sync.aligned.m16n8k16.row.col.f32.bf16.bf16.f32 "
        "{%0,%1,%2,%3}, {%4,%5,%6,%7}, {%8,%9}, {%0,%1,%2,%3};"
        : "+f"(c[0]), "+f"(c[1]), "+f"(c[2]), "+f"(c[3])
        : "r"(a[0]), "r"(a[1]), "r"(a[2]), "r"(a[3]), "r"(b0), "r"(b1));
}

// split 8 floats into packed bf16 hi / lo (uint4 each, elem0 in low half)
__device__ __forceinline__ void splitpack8(float4 a, float4 b, uint4& hh, uint4& ll) {
    float f[8] = {a.x, a.y, a.z, a.w, b.x, b.y, b.z, b.w};
    u32 hw[8], lw[8];
    #pragma unroll
    for (int i = 0; i < 8; ++i) {
        u32 hb = (u32)__bfloat16_as_ushort(__float2bfloat16_rn(f[i]));
        float hf = __uint_as_float(hb << 16);
        lw[i] = (u32)__bfloat16_as_ushort(__float2bfloat16_rn(f[i] - hf));
        hw[i] = hb;
    }
    hh = make_uint4(hw[0] | (hw[1] << 16), hw[2] | (hw[3] << 16),
                    hw[4] | (hw[5] << 16), hw[6] | (hw[7] << 16));
    ll = make_uint4(lw[0] | (lw[1] << 16), lw[2] | (lw[3] << 16),
                    lw[4] | (lw[5] << 16), lw[6] | (lw[7] << 16));
}

// pack (x,y) into bf16x2 hi word + residual lo word
__device__ __forceinline__ void packsplit2(float x, float y, u32& hi, u32& lo) {
    __nv_bfloat162 h = __floats2bfloat162_rn(x, y);
    hi = *reinterpret_cast<u32*>(&h);
    float2 hf = __bfloat1622float2(h);
    __nv_bfloat162 l = __floats2bfloat162_rn(x - hf.x, y - hf.y);
    lo = *reinterpret_cast<u32*>(&l);
}

// ---------------- kernel ----------------
__global__ void __launch_bounds__(NT, 3) causal_attn_kernel(
    const float* __restrict__ q, const float* __restrict__ k,
    const float* __restrict__ v, const float* __restrict__ bias,
    float* __restrict__ out)
{
    __shared__ __align__(128) char smem[SMEM_TOTAL];
    const u32 sb = smem_u32(smem);

    const int t    = threadIdx.x;
    const int lane = t & 31;
    const int w    = t >> 5;
    const int gid  = lane >> 2;      // 0..7
    const int tid4 = lane & 3;       // 0..3
    const int wrow = w << 4;         // warp's first S/O row (block-local)

    const int qt = (int)gridDim.x - 1 - (int)blockIdx.x;   // heavy first
    const int r0 = qt * BM;
    const int bh = blockIdx.y;
    const int b  = bh >> 3;
    const int h  = bh & 7;

    const float scale = 0.125f;
    const size_t base = (size_t)b * L_ * ROWS + (size_t)h * E_;
    const float* qb = q + base;
    const float* kb = k + base;
    const float* vb = v + base;
    float*       ob = out + base;

    // ---- Q prologue: fp32 -> bf16 hi/lo, swizzled smem ----
    {
        const int row = t >> 1, half = t & 1;
        const float* qrow = qb + (size_t)(r0 + row) * ROWS + 32 * half;
        #pragma unroll
        for (int i = 0; i < 4; ++i) {
            float4 a  = *(const float4*)(qrow + 8 * i);
            float4 b4 = *(const float4*)(qrow + 8 * i + 4);
            uint4 hh, ll;
            splitpack8(a, b4, hh, ll);
            int c = 4 * half + i;                     // 16B chunk index
            u32 off = (u32)(row * 128 + 16 * (c ^ (row & 7)));
            *reinterpret_cast<uint4*>(smem + OFF_QHI + off) = hh;
            *reinterpret_cast<uint4*>(smem + OFF_QLO + off) = ll;
        }
    }
    __syncthreads();

    // ---- A fragments of Q (held in registers for all tiles) ----
    u32 aH[4][4], aL[4][4];
    {
        const int rowL = wrow + (lane & 15);
        const int csel = lane >> 4;                   // 0/1: k-halves
        #pragma unroll
        for (int ks = 0; ks < 4; ++ks) {
            u32 off = (u32)(rowL * 128 + 16 * (((2 * ks + csel) ^ (rowL & 7))));
            ldsm4(aH[ks], sb + OFF_QHI + off);
            ldsm4(aL[ks], sb + OFF_QLO + off);
        }
    }
    __syncthreads();   // Q smem dead; tile region may be overwritten

    // ---- per-thread state ----
    float oF[8][4];                 // O fragments: 8 n-tiles (e) x 4 regs
    #pragma unroll
    for (int nt = 0; nt < 8; ++nt)
        #pragma unroll
        for (int i = 0; i < 4; ++i) oF[nt][i] = 0.f;
    float m1 = -3.0e38f, m2 = -3.0e38f, ls1 = 0.f, ls2 = 0.f;
    const int gr1 = r0 + wrow + gid;       // softmax/O row 1 (global)
    const int gr2 = gr1 + 8;

    const int nfull  = r0 >> 5;
    const int ntiles = nfull + 2;

    // K/V cooperative-load coords (16 contiguous floats per thread)
    const int krow = t >> 2, kq = t & 3;

    // prefetch tile 0
    float4 kpre[4], vpre[4];
    #pragma unroll
    for (int i = 0; i < 4; ++i) {
        kpre[i] = *(const float4*)(kb + (size_t)krow * ROWS + kq * 16 + i * 4);
        vpre[i] = *(const float4*)(vb + (size_t)krow * ROWS + kq * 16 + i * 4);
    }

    // B-fragment ldmatrix lane pieces (constant across tiles)
    const int bg    = lane >> 3;                         // matrix id 0..3
    const int bjoff = 8 * (bg >> 1) + (lane & 7);        // K-ldsm row helper
    const int bcs   = bg & 1;
    // V (trans) ldsm pieces
    const int vjoff = ((bg & 1) << 3) + (lane & 7);      // j within 16-group
    const int vcsel = bg >> 1;                           // chunk parity

    for (int tile = 0; tile < ntiles; ++tile) {
        const int j0 = tile << 5;
        __syncthreads();               // previous tile fully consumed

        // ---- STS K hi/lo + V hi/lo (swizzled bf16) ----
        {
            uint4 hh0, ll0, hh1, ll1;
            splitpack8(kpre[0], kpre[1], hh0, ll0);
            splitpack8(kpre[2], kpre[3], hh1, ll1);
            u32 o0 = (u32)(krow * 128 + 16 * ((2 * kq)     ^ (krow & 7)));
            u32 o1 = (u32)(krow * 128 + 16 * ((2 * kq + 1) ^ (krow & 7)));
            *reinterpret_cast<uint4*>(smem + OFF_KHI + o0) = hh0;
            *reinterpret_cast<uint4*>(smem + OFF_KHI + o1) = hh1;
            *reinterpret_cast<uint4*>(smem + OFF_KLO + o0) = ll0;
            *reinterpret_cast<uint4*>(smem + OFF_KLO + o1) = ll1;
            splitpack8(vpre[0], vpre[1], hh0, ll0);
            splitpack8(vpre[2], vpre[3], hh1, ll1);
            *reinterpret_cast<uint4*>(smem + OFF_VHI + o0) = hh0;
            *reinterpret_cast<uint4*>(smem + OFF_VHI + o1) = hh1;
            *reinterpret_cast<uint4*>(smem + OFF_VLO + o0) = ll0;
            *reinterpret_cast<uint4*>(smem + OFF_VLO + o1) = ll1;
        }
        __syncthreads();

        // ---- prefetch next K/V (latency hidden under mma) ----
        if (tile + 1 < ntiles) {
            const int jn = (tile + 1) << 5;
            #pragma unroll
            for (int i = 0; i < 4; ++i) {
                kpre[i] = *(const float4*)(kb + (size_t)(jn + krow) * ROWS + kq * 16 + i * 4);
                vpre[i] = *(const float4*)(vb + (size_t)(jn + krow) * ROWS + kq * 16 + i * 4);
            }
        }
        // bias for this thread's fragment cols
        float2 bb1[4], bb2[4];
        {
            const float* bp1 = bias + (size_t)gr1 * L_ + j0 + 2 * tid4;
            const float* bp2 = bias + (size_t)gr2 * L_ + j0 + 2 * tid4;
            #pragma unroll
            for (int nt = 0; nt < 4; ++nt) {
                bb1[nt] = __ldg((const float2*)(bp1 + 8 * nt));
                bb2[nt] = __ldg((const float2*)(bp2 + 8 * nt));
            }
        }

        // ---- S = Q K^T on tensor cores (bf16x3) ----
        float cS[4][4];
        #pragma unroll
        for (int nt = 0; nt < 4; ++nt)
            #pragma unroll
            for (int i = 0; i < 4; ++i) cS[nt][i] = 0.f;

        #pragma unroll
        for (int ks = 0; ks < 4; ++ks) {
            #pragma unroll
            for (int ntp = 0; ntp < 2; ++ntp) {
                const int jrow = 16 * ntp + bjoff;
                u32 off = (u32)(jrow * 128 + 16 * (((2 * ks + bcs) ^ (jrow & 7))));
                u32 bhm[4], blm[4];
                ldsm4(bhm, sb + OFF_KHI + off);
                ldsm4(blm, sb + OFF_KLO + off);
                mma16816(cS[2 * ntp],     aH[ks], bhm[0], bhm[1]);
                mma16816(cS[2 * ntp],     aH[ks], blm[0], blm[1]);
                mma16816(cS[2 * ntp],     aL[ks], bhm[0], bhm[1]);
                mma16816(cS[2 * ntp + 1], aH[ks], bhm[2], bhm[3]);
                mma16816(cS[2 * ntp + 1], aH[ks], blm[2], blm[3]);
                mma16816(cS[2 * ntp + 1], aL[ks], bhm[2], bhm[3]);
            }
        }

        // ---- softmax on fragments (rows gr1, gr2; 8 cols each) ----
        float tv1[8], tv2[8];
        #pragma unroll
        for (int nt = 0; nt < 4; ++nt) {
            tv1[2 * nt]     = (cS[nt][0] + bb1[nt].x) * scale;
            tv1[2 * nt + 1] = (cS[nt][1] + bb1[nt].y) * scale;
            tv2[2 * nt]     = (cS[nt][2] + bb2[nt].x) * scale;
            tv2[2 * nt + 1] = (cS[nt][3] + bb2[nt].y) * scale;
        }
        if (tile >= nfull) {
            #pragma unroll
            for (int nt = 0; nt < 4; ++nt) {
                int c0 = j0 + 8 * nt + 2 * tid4;
                if (c0     > gr1) tv1[2 * nt]     = -3.0e38f;
                if (c0 + 1 > gr1) tv1[2 * nt + 1] = -3.0e38f;
                if (c0     > gr2) tv2[2 * nt]     = -3.0e38f;
                if (c0 + 1 > gr2) tv2[2 * nt + 1] = -3.0e38f;
            }
        }
        float mx1 = tv1[0], mx2 = tv2[0];
        #pragma unroll
        for (int i = 1; i < 8; ++i) {
            mx1 = fmaxf(mx1, tv1[i]);
            mx2 = fmaxf(mx2, tv2[i]);
        }
        mx1 = fmaxf(mx1, __shfl_xor_sync(0xffffffffu, mx1, 1));
        mx1 = fmaxf(mx1, __shfl_xor_sync(0xffffffffu, mx1, 2));
        mx2 = fmaxf(mx2, __shfl_xor_sync(0xffffffffu, mx2, 1));
        mx2 = fmaxf(mx2, __shfl_xor_sync(0xffffffffu, mx2, 2));
        float mn1 = fmaxf(m1, mx1), mn2 = fmaxf(m2, mx2);
        float alpha1 = __expf(m1 - mn1), alpha2 = __expf(m2 - mn2);
        m1 = mn1; m2 = mn2;
        float ps1 = 0.f, ps2 = 0.f;
        #pragma unroll
        for (int i = 0; i < 8; ++i) {
            tv1[i] = __expf(tv1[i] - mn1); ps1 += tv1[i];
            tv2[i] = __expf(tv2[i] - mn2); ps2 += tv2[i];
        }
        ps1 += __shfl_xor_sync(0xffffffffu, ps1, 1);
        ps1 += __shfl_xor_sync(0xffffffffu, ps1, 2);
        ps2 += __shfl_xor_sync(0xffffffffu, ps2, 1);
        ps2 += __shfl_xor_sync(0xffffffffu, ps2, 2);
        ls1 = ls1 * alpha1 + ps1;
        ls2 = ls2 * alpha2 + ps2;

        // ---- pack P into A fragments (hi/lo), all register-local ----
        u32 aPh[2][4], aPl[2][4];
        #pragma unroll
        for (int ks2 = 0; ks2 < 2; ++ks2) {
            packsplit2(tv1[4 * ks2],     tv1[4 * ks2 + 1], aPh[ks2][0], aPl[ks2][0]);
            packsplit2(tv2[4 * ks2],     tv2[4 * ks2 + 1], aPh[ks2][1], aPl[ks2][1]);
            packsplit2(tv1[4 * ks2 + 2], tv1[4 * ks2 + 3], aPh[ks2][2], aPl[ks2][2]);
            packsplit2(tv2[4 * ks2 + 2], tv2[4 * ks2 + 3], aPh[ks2][3], aPl[ks2][3]);
        }

        // ---- O rescale by alpha (rows register-local to this lane) ----
        #pragma unroll
        for (int nt = 0; nt < 8; ++nt) {
            oF[nt][0] *= alpha1;
            oF[nt][1] *= alpha1;
            oF[nt][2] *= alpha2;
            oF[nt][3] *= alpha2;
        }

        // ---- O += P V on tensor cores (Ph*Vh + Ph*Vl + Pl*Vh) ----
        #pragma unroll
        for (int ks2 = 0; ks2 < 2; ++ks2) {
            #pragma unroll
            for (int np = 0; np < 4; ++np) {
                const int jrow = 16 * ks2 + vjoff;
                u32 off = (u32)(jrow * 128 + 16 * (((2 * np + vcsel) ^ (jrow & 7))));
                u32 vh[4], vl[4];
                ldsm4t(vh, sb + OFF_VHI + off);
                ldsm4t(vl, sb + OFF_VLO + off);
                mma16816(oF[2 * np],     aPh[ks2], vh[0], vh[1]);
                mma16816(oF[2 * np],     aPh[ks2], vl[0], vl[1]);
                mma16816(oF[2 * np],     aPl[ks2], vh[0], vh[1]);
                mma16816(oF[2 * np + 1], aPh[ks2], vh[2], vh[3]);
                mma16816(oF[2 * np + 1], aPh[ks2], vl[2], vl[3]);
                mma16816(oF[2 * np + 1], aPl[ks2], vh[2], vh[3]);
            }
        }
    }

    // ---- epilogue: normalize (register-local) and store ----
    {
        float inv1 = 1.0f / ls1;
        float inv2 = 1.0f / ls2;
        float* orow1 = ob + (size_t)gr1 * ROWS;
        float* orow2 = ob + (size_t)gr2 * ROWS;
        #pragma unroll
        for (int nt = 0; nt < 8; ++nt) {
            int e = 8 * nt + 2 * tid4;
            *(float2*)(orow1 + e) = make_float2(oF[nt][0] * inv1, oF[nt][1] * inv1);
            *(float2*)(orow2 + e) = make_float2(oF[nt][2] * inv2, oF[nt][3] * inv2);
        }
    }
}

extern "C" void kernel_launch(void* const* d_in, const int* in_sizes, int n_in,
                              void* d_out, int out_size)
{
    const float* q    = (const float*)d_in[0];  // (B,L,H,E)
    const float* k    = (const float*)d_in[1];  // (B,L,H,E)
    const float* v    = (const float*)d_in[2];  // (B,L,H,E)
    // d_in[3] = attn_mask: fixed triu(k=1), handled analytically
    const float* bias = (const float*)d_in[4];  // (L,L)

    float* out = (float*)d_out;                 // (B,L,H,E) fp32

    dim3 grid(L_ / BM, B_ * H_);
    causal_attn_kernel<<<grid, NT>>>(q, k, v, bias, out);
}

// round 9
// speedup vs baseline: 3.4677x; 1.1062x over previous
#include <cuda_runtime.h>
#include <cuda_bf16.h>
#include <cstdint>

typedef unsigned long long ull;
typedef unsigned int u32;

#define B_    4
#define L_    2048
#define H_    8
#define E_    64
#define BM    128         // query rows per block (32 per warp, 2 row-tiles)
#define BN    32          // keys per tile
#define NT    128         // 4 warps
#define ROWS  512         // H_*E_ float stride between consecutive l

// ---- static smem layout (bytes). Q prologue aliases the K/V region. ----
#define OFF_KHI  0                 // 32 x 128B bf16 (swizzled)
#define OFF_KLO  4096
#define OFF_VHI  8192              // 32 x 128B bf16 (swizzled)
#define OFF_VLO  12288
#define SMEM_TOTAL 16384
#define OFF_Q    0                 // 128 x 128B (prologue passes, aliased)

// ---------------- tensor-core wrappers (baseline sm_80+ ISA) ----------------
__device__ __forceinline__ u32 smem_u32(const void* p) {
    u32 a;
    asm("{ .reg .u64 t; cvta.to.shared.u64 t, %1; cvt.u32.u64 %0, t; }"
        : "=r"(a) : "l"(p));
    return a;
}
__device__ __forceinline__ void ldsm4(u32 r[4], u32 addr) {
    asm volatile("ldmatrix.sync.aligned.m8n8.x4.shared.b16 {%0,%1,%2,%3}, [%4];"
                 : "=r"(r[0]), "=r"(r[1]), "=r"(r[2]), "=r"(r[3]) : "r"(addr));
}
__device__ __forceinline__ void ldsm4t(u32 r[4], u32 addr) {
    asm volatile("ldmatrix.sync.aligned.m8n8.x4.trans.shared.b16 {%0,%1,%2,%3}, [%4];"
                 : "=r"(r[0]), "=r"(r[1]), "=r"(r[2]), "=r"(r[3]) : "r"(addr));
}
__device__ __forceinline__ void mma16816(float c[4], const u32 a[4], u32 b0, u32 b1) {
    asm volatile(
        "mma.sync.aligned.m16n8k16.row.col.f32.bf16.bf16.f32 "
        "{%0,%1,%2,%3}, {%4,%5,%6,%7}, {%8,%9}, {%0,%1,%2,%3};"
        : "+f"(c[0]), "+f"(c[1]), "+f"(c[2]), "+f"(c[3])
        : "r"(a[0]), "r"(a[1]), "r"(a[2]), "r"(a[3]), "r"(b0), "r"(b1));
}

// split 8 floats into packed bf16 hi / lo (uint4 each, elem0 in low half)
__device__ __forceinline__ void splitpack8(float4 a, float4 b, uint4& hh, uint4& ll) {
    float f[8] = {a.x, a.y, a.z, a.w, b.x, b.y, b.z, b.w};
    u32 hw[8], lw[8];
    #pragma unroll
    for (int i = 0; i < 8; ++i) {
        u32 hb = (u32)__bfloat16_as_ushort(__float2bfloat16_rn(f[i]));
        float hf = __uint_as_float(hb << 16);
        lw[i] = (u32)__bfloat16_as_ushort(__float2bfloat16_rn(f[i] - hf));
        hw[i] = hb;
    }
    hh = make_uint4(hw[0] | (hw[1] << 16), hw[2] | (hw[3] << 16),
                    hw[4] | (hw[5] << 16), hw[6] | (hw[7] << 16));
    ll = make_uint4(lw[0] | (lw[1] << 16), lw[2] | (lw[3] << 16),
                    lw[4] | (lw[5] << 16), lw[6] | (lw[7] << 16));
}

// pack (x,y) into bf16x2 hi word + residual lo word
__device__ __forceinline__ void packsplit2(float x, float y, u32& hi, u32& lo) {
    __nv_bfloat162 h = __floats2bfloat162_rn(x, y);
    hi = *reinterpret_cast<u32*>(&h);
    float2 hf = __bfloat1622float2(h);
    __nv_bfloat162 l = __floats2bfloat162_rn(x - hf.x, y - hf.y);
    lo = *reinterpret_cast<u32*>(&l);
}

// ---------------- kernel ----------------
__global__ void __launch_bounds__(NT, 2) causal_attn_kernel(
    const float* __restrict__ q, const float* __restrict__ k,
    const float* __restrict__ v, const float* __restrict__ bias,
    float* __restrict__ out)
{
    __shared__ __align__(128) char smem[SMEM_TOTAL];
    const u32 sb = smem_u32(smem);

    const int t    = threadIdx.x;
    const int lane = t & 31;
    const int w    = t >> 5;
    const int gid  = lane >> 2;      // 0..7
    const int tid4 = lane & 3;       // 0..3
    const int wrow = w << 5;         // warp's first S/O row (32 rows per warp)

    const int qt = (int)gridDim.x - 1 - (int)blockIdx.x;   // heavy first
    const int r0 = qt * BM;
    const int bh = blockIdx.y;
    const int b  = bh >> 3;
    const int h  = bh & 7;

    const float scale = 0.125f;
    const size_t base = (size_t)b * L_ * ROWS + (size_t)h * E_;
    const float* qb = q + base;
    const float* kb = k + base;
    const float* vb = v + base;
    float*       ob = out + base;

    // ---- Q prologue: two passes (hi then lo) through 16KB aliased smem ----
    u32 aH[2][4][4], aL[2][4][4];
    const int rowL0 = wrow + (lane & 15);
    const int csel  = lane >> 4;                  // 0/1: k-half select
    #pragma unroll
    for (int pass = 0; pass < 2; ++pass) {
        const float* qrow = qb + (size_t)(r0 + t) * ROWS;
        #pragma unroll
        for (int c = 0; c < 8; ++c) {
            float4 a  = *(const float4*)(qrow + 8 * c);
            float4 b4 = *(const float4*)(qrow + 8 * c + 4);
            uint4 hh, ll;
            splitpack8(a, b4, hh, ll);
            u32 off = (u32)(t * 128 + 16 * (c ^ (t & 7)));
            *reinterpret_cast<uint4*>(smem + OFF_Q + off) = pass ? ll : hh;
        }
        __syncthreads();
        #pragma unroll
        for (int rt = 0; rt < 2; ++rt) {
            const int rowL = rowL0 + 16 * rt;
            #pragma unroll
            for (int ks = 0; ks < 4; ++ks) {
                u32 off = (u32)(rowL * 128 + 16 * (((2 * ks + csel) ^ (rowL & 7))));
                if (pass) ldsm4(aL[rt][ks], sb + OFF_Q + off);
                else      ldsm4(aH[rt][ks], sb + OFF_Q + off);
            }
        }
        __syncthreads();
    }

    // ---- per-thread state ----
    float oF[2][8][4];
    #pragma unroll
    for (int rt = 0; rt < 2; ++rt)
        #pragma unroll
        for (int nt = 0; nt < 8; ++nt)
            #pragma unroll
            for (int i = 0; i < 4; ++i) oF[rt][nt][i] = 0.f;
    float m1[2]  = {-3.0e38f, -3.0e38f};
    float m2[2]  = {-3.0e38f, -3.0e38f};
    float ls1[2] = {0.f, 0.f};
    float ls2[2] = {0.f, 0.f};

    const int nfull  = r0 >> 5;
    const int ntiles = nfull + 4;

    // K/V cooperative-load coords (16 contiguous floats per thread)
    const int krow = t >> 2, kq = t & 3;

    // prefetch tile 0
    float4 kpre[4], vpre[4];
    #pragma unroll
    for (int i = 0; i < 4; ++i) {
        kpre[i] = *(const float4*)(kb + (size_t)krow * ROWS + kq * 16 + i * 4);
        vpre[i] = *(const float4*)(vb + (size_t)krow * ROWS + kq * 16 + i * 4);
    }

    // B-fragment ldmatrix lane pieces (constant across tiles)
    const int bg    = lane >> 3;
    const int bjoff = 8 * (bg >> 1) + (lane & 7);
    const int bcs   = bg & 1;
    const int vjoff = ((bg & 1) << 3) + (lane & 7);
    const int vcsel = bg >> 1;

    for (int tile = 0; tile < ntiles; ++tile) {
        const int j0 = tile << 5;
        __syncthreads();               // previous tile fully consumed

        // ---- STS K hi/lo + V hi/lo (swizzled bf16) ----
        {
            uint4 hh0, ll0, hh1, ll1;
            splitpack8(kpre[0], kpre[1], hh0, ll0);
            splitpack8(kpre[2], kpre[3], hh1, ll1);
            u32 o0 = (u32)(krow * 128 + 16 * ((2 * kq)     ^ (krow & 7)));
            u32 o1 = (u32)(krow * 128 + 16 * ((2 * kq + 1) ^ (krow & 7)));
            *reinterpret_cast<uint4*>(smem + OFF_KHI + o0) = hh0;
            *reinterpret_cast<uint4*>(smem + OFF_KHI + o1) = hh1;
            *reinterpret_cast<uint4*>(smem + OFF_KLO + o0) = ll0;
            *reinterpret_cast<uint4*>(smem + OFF_KLO + o1) = ll1;
            splitpack8(vpre[0], vpre[1], hh0, ll0);
            splitpack8(vpre[2], vpre[3], hh1, ll1);
            *reinterpret_cast<uint4*>(smem + OFF_VHI + o0) = hh0;
            *reinterpret_cast<uint4*>(smem + OFF_VHI + o1) = hh1;
            *reinterpret_cast<uint4*>(smem + OFF_VLO + o0) = ll0;
            *reinterpret_cast<uint4*>(smem + OFF_VLO + o1) = ll1;
        }
        __syncthreads();

        // ---- prefetch next K/V (latency hidden under mma) ----
        if (tile + 1 < ntiles) {
            const int jn = (tile + 1) << 5;
            #pragma unroll
            for (int i = 0; i < 4; ++i) {
                kpre[i] = *(const float4*)(kb + (size_t)(jn + krow) * ROWS + kq * 16 + i * 4);
                vpre[i] = *(const float4*)(vb + (size_t)(jn + krow) * ROWS + kq * 16 + i * 4);
            }
        }

        // ---- S = Q K^T : each B-fragment reused for both row-tiles ----
        float cS[2][4][4];
        #pragma unroll
        for (int rt = 0; rt < 2; ++rt)
            #pragma unroll
            for (int nt = 0; nt < 4; ++nt)
                #pragma unroll
                for (int i = 0; i < 4; ++i) cS[rt][nt][i] = 0.f;

        #pragma unroll
        for (int ks = 0; ks < 4; ++ks) {
            #pragma unroll
            for (int ntp = 0; ntp < 2; ++ntp) {
                const int jrow = 16 * ntp + bjoff;
                u32 off = (u32)(jrow * 128 + 16 * (((2 * ks + bcs) ^ (jrow & 7))));
                u32 bhm[4], blm[4];
                ldsm4(bhm, sb + OFF_KHI + off);
                ldsm4(blm, sb + OFF_KLO + off);
                #pragma unroll
                for (int rt = 0; rt < 2; ++rt) {
                    mma16816(cS[rt][2 * ntp],     aH[rt][ks], bhm[0], bhm[1]);
                    mma16816(cS[rt][2 * ntp],     aH[rt][ks], blm[0], blm[1]);
                    mma16816(cS[rt][2 * ntp],     aL[rt][ks], bhm[0], bhm[1]);
                    mma16816(cS[rt][2 * ntp + 1], aH[rt][ks], bhm[2], bhm[3]);
                    mma16816(cS[rt][2 * ntp + 1], aH[rt][ks], blm[2], blm[3]);
                    mma16816(cS[rt][2 * ntp + 1], aL[rt][ks], bhm[2], bhm[3]);
                }
            }
        }

        // ---- softmax + P-fragment pack per row-tile ----
        u32 aPh[2][2][4], aPl[2][2][4];
        float alpha1[2], alpha2[2];
        #pragma unroll
        for (int rt = 0; rt < 2; ++rt) {
            const int gr1 = r0 + wrow + 16 * rt + gid;
            const int gr2 = gr1 + 8;
            float tv1[8], tv2[8];
            {
                const float* bp1 = bias + (size_t)gr1 * L_ + j0 + 2 * tid4;
                const float* bp2 = bias + (size_t)gr2 * L_ + j0 + 2 * tid4;
                #pragma unroll
                for (int nt = 0; nt < 4; ++nt) {
                    float2 b1 = __ldg((const float2*)(bp1 + 8 * nt));
                    float2 b2 = __ldg((const float2*)(bp2 + 8 * nt));
                    tv1[2 * nt]     = (cS[rt][nt][0] + b1.x) * scale;
                    tv1[2 * nt + 1] = (cS[rt][nt][1] + b1.y) * scale;
                    tv2[2 * nt]     = (cS[rt][nt][2] + b2.x) * scale;
                    tv2[2 * nt + 1] = (cS[rt][nt][3] + b2.y) * scale;
                }
            }
            if (tile >= nfull) {
                #pragma unroll
                for (int nt = 0; nt < 4; ++nt) {
                    int c0 = j0 + 8 * nt + 2 * tid4;
                    if (c0     > gr1) tv1[2 * nt]     = -3.0e38f;
                    if (c0 + 1 > gr1) tv1[2 * nt + 1] = -3.0e38f;
                    if (c0     > gr2) tv2[2 * nt]     = -3.0e38f;
                    if (c0 + 1 > gr2) tv2[2 * nt + 1] = -3.0e38f;
                }
            }
            float mx1 = tv1[0], mx2 = tv2[0];
            #pragma unroll
            for (int i = 1; i < 8; ++i) {
                mx1 = fmaxf(mx1, tv1[i]);
                mx2 = fmaxf(mx2, tv2[i]);
            }
            mx1 = fmaxf(mx1, __shfl_xor_sync(0xffffffffu, mx1, 1));
            mx1 = fmaxf(mx1, __shfl_xor_sync(0xffffffffu, mx1, 2));
            mx2 = fmaxf(mx2, __shfl_xor_sync(0xffffffffu, mx2, 1));
            mx2 = fmaxf(mx2, __shfl_xor_sync(0xffffffffu, mx2, 2));
            float mn1 = fmaxf(m1[rt], mx1), mn2 = fmaxf(m2[rt], mx2);
            alpha1[rt] = __expf(m1[rt] - mn1);
            alpha2[rt] = __expf(m2[rt] - mn2);
            m1[rt] = mn1; m2[rt] = mn2;
            float ps1 = 0.f, ps2 = 0.f;
            #pragma unroll
            for (int i = 0; i < 8; ++i) {
                tv1[i] = __expf(tv1[i] - mn1); ps1 += tv1[i];
                tv2[i] = __expf(tv2[i] - mn2); ps2 += tv2[i];
            }
            ps1 += __shfl_xor_sync(0xffffffffu, ps1, 1);
            ps1 += __shfl_xor_sync(0xffffffffu, ps1, 2);
            ps2 += __shfl_xor_sync(0xffffffffu, ps2, 1);
            ps2 += __shfl_xor_sync(0xffffffffu, ps2, 2);
            ls1[rt] = ls1[rt] * alpha1[rt] + ps1;
            ls2[rt] = ls2[rt] * alpha2[rt] + ps2;

            #pragma unroll
            for (int ks2 = 0; ks2 < 2; ++ks2) {
                packsplit2(tv1[4 * ks2],     tv1[4 * ks2 + 1], aPh[rt][ks2][0], aPl[rt][ks2][0]);
                packsplit2(tv2[4 * ks2],     tv2[4 * ks2 + 1], aPh[rt][ks2][1], aPl[rt][ks2][1]);
                packsplit2(tv1[4 * ks2 + 2], tv1[4 * ks2 + 3], aPh[rt][ks2][2], aPl[rt][ks2][2]);
                packsplit2(tv2[4 * ks2 + 2], tv2[4 * ks2 + 3], aPh[rt][ks2][3], aPl[rt][ks2][3]);
            }
            // O rescale
            #pragma unroll
            for (int nt = 0; nt < 8; ++nt) {
                oF[rt][nt][0] *= alpha1[rt];
                oF[rt][nt][1] *= alpha1[rt];
                oF[rt][nt][2] *= alpha2[rt];
                oF[rt][nt][3] *= alpha2[rt];
            }
        }

        // ---- O += P V : each V fragment reused for both row-tiles ----
        #pragma unroll
        for (int ks2 = 0; ks2 < 2; ++ks2) {
            #pragma unroll
            for (int np = 0; np < 4; ++np) {
                const int jrow = 16 * ks2 + vjoff;
                u32 off = (u32)(jrow * 128 + 16 * (((2 * np + vcsel) ^ (jrow & 7))));
                u32 vh[4], vl[4];
                ldsm4t(vh, sb + OFF_VHI + off);
                ldsm4t(vl, sb + OFF_VLO + off);
                #pragma unroll
                for (int rt = 0; rt < 2; ++rt) {
                    mma16816(oF[rt][2 * np],     aPh[rt][ks2], vh[0], vh[1]);
                    mma16816(oF[rt][2 * np],     aPh[rt][ks2], vl[0], vl[1]);
                    mma16816(oF[rt][2 * np],     aPl[rt][ks2], vh[0], vh[1]);
                    mma16816(oF[rt][2 * np + 1], aPh[rt][ks2], vh[2], vh[3]);
                    mma16816(oF[rt][2 * np + 1], aPh[rt][ks2], vl[2], vl[3]);
                    mma16816(oF[rt][2 * np + 1], aPl[rt][ks2], vh[2], vh[3]);
                }
            }
        }
    }

    // ---- epilogue: normalize (register-local) and store ----
    #pragma unroll
    for (int rt = 0; rt < 2; ++rt) {
        const int gr1 = r0 + wrow + 16 * rt + gid;
        const int gr2 = gr1 + 8;
        float inv1 = 1.0f / ls1[rt];
        float inv2 = 1.0f / ls2[rt];
        float* orow1 = ob + (size_t)gr1 * ROWS;
        float* orow2 = ob + (size_t)gr2 * ROWS;
        #pragma unroll
        for (int nt = 0; nt < 8; ++nt) {
            int e = 8 * nt + 2 * tid4;
            *(float2*)(orow1 + e) = make_float2(oF[rt][nt][0] * inv1, oF[rt][nt][1] * inv1);
            *(float2*)(orow2 + e) = make_float2(oF[rt][nt][2] * inv2, oF[rt][nt][3] * inv2);
        }
    }
}

extern "C" void kernel_launch(void* const* d_in, const int* in_sizes, int n_in,
                              void* d_out, int out_size)
{
    const float* q    = (const float*)d_in[0];  // (B,L,H,E)
    const float* k    = (const float*)d_in[1];  // (B,L,H,E)
    const float* v    = (const float*)d_in[2];  // (B,L,H,E)
    // d_in[3] = attn_mask: fixed triu(k=1), handled analytically
    const float* bias = (const float*)d_in[4];  // (L,L)

    float* out = (float*)d_out;                 // (B,L,H,E) fp32

    dim3 grid(L_ / BM, B_ * H_);
    causal_attn_kernel<<<grid, NT>>>(q, k, v, bias, out);
}